// round 7
// baseline (speedup 1.0000x reference)
#include <cuda_runtime.h>
#include <math.h>

#define NTOK  (8*64*64)

// Scratch (device globals)
__device__ float g_hs[(size_t)NTOK * 224];   // residual + attn output
__device__ float g_w1t[224 * 896];           // tf32 mlp1_w
__device__ float g_w2t[896 * 224];           // tf32 mlp2_w
__device__ float g_wbig[112 * 896];          // tf32 [Q|K|V|R] weights
__device__ float g_wpt[224 * 224];           // tf32 attn_proj_w
__device__ float g_bbig[896];                // [qkv_b | res_proj_b]

__device__ __forceinline__ unsigned f2tf32(float x) {
    unsigned r;
    asm("cvt.rna.tf32.f32 %0, %1;" : "=r"(r) : "f"(x));
    return r;
}
__device__ __forceinline__ float rtf(float x) { return __uint_as_float(f2tf32(x)); }

__device__ __forceinline__ void mma_tf32(float* c,
        unsigned a0, unsigned a1, unsigned a2, unsigned a3,
        unsigned b0, unsigned b1) {
    asm("mma.sync.aligned.m16n8k8.row.col.f32.tf32.tf32.f32 "
        "{%0,%1,%2,%3}, {%4,%5,%6,%7}, {%8,%9}, {%0,%1,%2,%3};"
        : "+f"(c[0]), "+f"(c[1]), "+f"(c[2]), "+f"(c[3])
        : "r"(a0), "r"(a1), "r"(a2), "r"(a3), "r"(b0), "r"(b1));
}

// ---------------------------------------------------------------------------
// K0: round weights to tf32, build combined [qkv|res] weight + bias
// ---------------------------------------------------------------------------
__global__ void k_prep(const float* __restrict__ W1,   const float* __restrict__ W2,
                       const float* __restrict__ Wqkv, const float* __restrict__ Wrp,
                       const float* __restrict__ Wp,
                       const float* __restrict__ bqkv, const float* __restrict__ brp) {
    int i = blockIdx.x * 1024 + threadIdx.x;
    if (i < 224 * 896) { g_w1t[i] = rtf(W1[i]); g_w2t[i] = rtf(W2[i]); }
    if (i < 112 * 896) {
        int r = i / 896, c = i - r * 896;
        float v = (c < 672) ? Wqkv[r * 672 + c] : Wrp[r * 224 + (c - 672)];
        g_wbig[i] = rtf(v);
    }
    if (i < 224 * 224) g_wpt[i] = rtf(Wp[i]);
    if (i < 896) g_bbig[i] = (i < 672) ? bqkv[i] : brp[i - 672];
}

// ---------------------------------------------------------------------------
// K3: fused LN1 + Q/K/R GEMM + pooling + attention + V GEMM + proj + residual
// 2048 blocks x 384 threads (12 warps), 2 CTAs/SM.
// smem: Xs[64][116] | BIG[19904] (Kt 224x72, Qt 16x236; later P 64x76, V 64x232)
//       | stats 256
// Ot (16x236) aliases Xs after V-compute.
// ---------------------------------------------------------------------------
#define XS_STR 116
#define KT_STR 72
#define QT_STR 236
#define VR_STR 232
#define OT_STR 236
#define P_STR  76
#define XS_N   (64 * XS_STR)              // 7424
#define KT_N   (224 * KT_STR)             // 16128
#define QT_N   (16 * QT_STR)              // 3776
#define BIG_N  (KT_N + QT_N)              // 19904
#define SMEM3  ((XS_N + BIG_N + 256) * 4) // 110336 B

__global__ void __launch_bounds__(384, 2) k_attn(
        const float* __restrict__ hidden,
        const float* __restrict__ ln1g, const float* __restrict__ ln1b,
        const float* __restrict__ bp) {
    extern __shared__ float sm[];
    float* Xs   = sm;                 // window / later Ot
    float* Kt   = sm + XS_N;          // K [d][t]
    float* Qt   = Kt + KT_N;          // pooled Q [q][d]
    float* P    = Kt;                 // softmax probs (alias, post-K-death)
    float* Vr   = Kt + 4864;          // V [t][d] (alias, post-scores)
    float* smax = sm + XS_N + BIG_N;  // [64][2]
    float* ssum = smax + 128;         // [64][2]
    float* Ot   = sm;                 // attn out [q][d] (alias Xs)

    int wi = blockIdx.x;
    int b  = wi >> 8;
    int r  = wi & 255;
    int wy = r >> 4, wx = r & 15;
    int tid  = threadIdx.x;
    int warp = tid >> 5, lane = tid & 31;
    int g = lane >> 2, tig = lane & 3;

    // ---- stage raw window ----
    for (int e = tid; e < 64 * 28; e += 384) {
        int t = e / 28, c4 = (e - t * 28) * 4;
        int y = wy * 8 + (t >> 3), x = wx * 8 + (t & 7);
        *(float4*)&Xs[t * XS_STR + c4] =
            *(const float4*)&hidden[(((size_t)b * 128 + y) * 128 + x) * 112 + c4];
    }
    __syncthreads();

    // ---- LN1 in place (warp per token), tf32-rounded ----
    {
        float gg0 = ln1g[lane], gg1 = ln1g[lane + 32], gg2 = ln1g[lane + 64];
        float bb0 = ln1b[lane], bb1 = ln1b[lane + 32], bb2 = ln1b[lane + 64];
        float gg3 = 0.f, bb3 = 0.f;
        if (lane < 16) { gg3 = ln1g[lane + 96]; bb3 = ln1b[lane + 96]; }
        for (int t = warp; t < 64; t += 12) {
            float* row = Xs + t * XS_STR;
            float v0 = row[lane], v1 = row[lane + 32], v2 = row[lane + 64];
            float v3 = (lane < 16) ? row[lane + 96] : 0.f;
            float s = v0 + v1 + v2 + v3;
            #pragma unroll
            for (int o = 16; o; o >>= 1) s += __shfl_xor_sync(~0u, s, o);
            float m = s * (1.f / 112.f);
            float d0 = v0 - m, d1 = v1 - m, d2 = v2 - m;
            float d3 = (lane < 16) ? v3 - m : 0.f;
            float q = d0*d0 + d1*d1 + d2*d2 + d3*d3;
            #pragma unroll
            for (int o = 16; o; o >>= 1) q += __shfl_xor_sync(~0u, q, o);
            float rs = rsqrtf(q * (1.f / 112.f) + 1e-6f);
            row[lane]      = rtf(d0 * rs * gg0 + bb0);
            row[lane + 32] = rtf(d1 * rs * gg1 + bb1);
            row[lane + 64] = rtf(d2 * rs * gg2 + bb2);
            if (lane < 16) row[lane + 96] = rtf(d3 * rs * gg3 + bb3);
        }
    }
    __syncthreads();

    // ---- GEMM1: Q|K|R, N=672, K=112; warp-per-matrix, 2 m-passes ----
    {
        const unsigned* Xb = (const unsigned*)Xs;
        const unsigned* Wb = (const unsigned*)g_wbig;
        int matsel  = warp >> 2;          // 0=Q, 1=K, 2=R
        int within  = warp & 3;
        int colbase = (matsel == 2 ? 672 : matsel * 224) + within * 56;
        #pragma unroll 1
        for (int mp = 0; mp < 2; mp++) {
            float acc[2][7][4];
            #pragma unroll
            for (int j = 0; j < 7; j++) {
                int col = colbase + j * 8;
                float bv0 = g_bbig[col + 2 * tig];
                float bv1 = g_bbig[col + 2 * tig + 1];
                #pragma unroll
                for (int mtl = 0; mtl < 2; mtl++) {
                    acc[mtl][j][0] = bv0; acc[mtl][j][1] = bv1;
                    acc[mtl][j][2] = bv0; acc[mtl][j][3] = bv1;
                }
            }
            for (int kc = 0; kc < 112; kc += 8) {
                unsigned a[2][4];
                #pragma unroll
                for (int mtl = 0; mtl < 2; mtl++) {
                    int r0 = (mp * 32 + mtl * 16 + g) * XS_STR + kc;
                    int r1 = r0 + 8 * XS_STR;
                    a[mtl][0] = Xb[r0 + tig];
                    a[mtl][1] = Xb[r1 + tig];
                    a[mtl][2] = Xb[r0 + tig + 4];
                    a[mtl][3] = Xb[r1 + tig + 4];
                }
                #pragma unroll
                for (int j = 0; j < 7; j++) {
                    int col = colbase + j * 8 + g;
                    unsigned b0 = Wb[(kc + tig) * 896 + col];
                    unsigned b1 = Wb[(kc + tig + 4) * 896 + col];
                    mma_tf32(acc[0][j], a[0][0], a[0][1], a[0][2], a[0][3], b0, b1);
                    mma_tf32(acc[1][j], a[1][0], a[1][1], a[1][2], a[1][3], b0, b1);
                }
            }
            if (matsel == 1) {            // K -> Kt[d][t] transpose
                #pragma unroll
                for (int mtl = 0; mtl < 2; mtl++)
                    #pragma unroll
                    for (int j = 0; j < 7; j++) {
                        int lc  = within * 56 + j * 8;
                        int t0r = mp * 32 + mtl * 16 + g;
                        Kt[(lc + 2*tig)     * KT_STR + t0r]     = rtf(acc[mtl][j][0]);
                        Kt[(lc + 2*tig + 1) * KT_STR + t0r]     = rtf(acc[mtl][j][1]);
                        Kt[(lc + 2*tig)     * KT_STR + t0r + 8] = rtf(acc[mtl][j][2]);
                        Kt[(lc + 2*tig + 1) * KT_STR + t0r + 8] = rtf(acc[mtl][j][3]);
                    }
            } else {                      // Q or R: 2x2 pool in regs
                #pragma unroll
                for (int mtl = 0; mtl < 2; mtl++)
                    #pragma unroll
                    for (int j = 0; j < 7; j++) {
                        float m0 = fmaxf(acc[mtl][j][0], acc[mtl][j][2]);
                        float m1 = fmaxf(acc[mtl][j][1], acc[mtl][j][3]);
                        m0 = fmaxf(m0, __shfl_xor_sync(~0u, m0, 4));
                        m1 = fmaxf(m1, __shfl_xor_sync(~0u, m1, 4));
                        if (!(g & 1)) {
                            int q = (mp * 2 + mtl) * 4 + (g >> 1);
                            if (matsel == 0) {
                                int lc = colbase + j * 8 + 2 * tig;
                                *(float2*)&Qt[q * QT_STR + lc] =
                                    make_float2(rtf(m0), rtf(m1));
                            } else {
                                int lc = colbase - 672 + j * 8 + 2 * tig;
                                int y2 = wy * 4 + (q >> 2), x2 = wx * 4 + (q & 3);
                                *(float2*)&g_hs[(((size_t)b * 64 + y2) * 64 + x2) * 224 + lc] =
                                    make_float2(m0, m1);
                            }
                        }
                    }
            }
        }
    }
    __syncthreads();

    // ---- scores + in-register softmax (8 warps) ----
    const float scale = 0.13363062095621219f;   // 56^-0.5
    bool sa = (warp < 8);
    int sh = warp >> 1, snh = warp & 1;
    float sc[4][4];
    if (sa) {
        const unsigned* Qb = (const unsigned*)Qt;
        const unsigned* Kb = (const unsigned*)Kt;
        #pragma unroll
        for (int j = 0; j < 4; j++)
            #pragma unroll
            for (int e = 0; e < 4; e++) sc[j][e] = 0.f;
        #pragma unroll
        for (int kc = 0; kc < 56; kc += 8) {
            int kd = sh * 56 + kc;
            unsigned a0 = Qb[g * QT_STR + kd + tig];
            unsigned a1 = Qb[(g + 8) * QT_STR + kd + tig];
            unsigned a2 = Qb[g * QT_STR + kd + tig + 4];
            unsigned a3 = Qb[(g + 8) * QT_STR + kd + tig + 4];
            #pragma unroll
            for (int j = 0; j < 4; j++) {
                int n0 = snh * 32 + j * 8;
                unsigned b0 = Kb[(kd + tig) * KT_STR + n0 + g];
                unsigned b1 = Kb[(kd + tig + 4) * KT_STR + n0 + g];
                mma_tf32(sc[j], a0, a1, a2, a3, b0, b1);
            }
        }
        float m0 = -1e30f, m1 = -1e30f;
        #pragma unroll
        for (int j = 0; j < 4; j++) {
            sc[j][0] *= scale; sc[j][1] *= scale;
            sc[j][2] *= scale; sc[j][3] *= scale;
            m0 = fmaxf(m0, fmaxf(sc[j][0], sc[j][1]));
            m1 = fmaxf(m1, fmaxf(sc[j][2], sc[j][3]));
        }
        m0 = fmaxf(m0, __shfl_xor_sync(~0u, m0, 1));
        m0 = fmaxf(m0, __shfl_xor_sync(~0u, m0, 2));
        m1 = fmaxf(m1, __shfl_xor_sync(~0u, m1, 1));
        m1 = fmaxf(m1, __shfl_xor_sync(~0u, m1, 2));
        if (tig == 0) {
            smax[(sh * 16 + g) * 2 + snh]     = m0;
            smax[(sh * 16 + g + 8) * 2 + snh] = m1;
        }
    }
    __syncthreads();
    if (sa) {
        int r0 = sh * 16 + g, r1 = r0 + 8;
        float M0 = fmaxf(smax[r0 * 2], smax[r0 * 2 + 1]);
        float M1 = fmaxf(smax[r1 * 2], smax[r1 * 2 + 1]);
        float s0 = 0.f, s1 = 0.f;
        #pragma unroll
        for (int j = 0; j < 4; j++) {
            sc[j][0] = __expf(sc[j][0] - M0); sc[j][1] = __expf(sc[j][1] - M0);
            sc[j][2] = __expf(sc[j][2] - M1); sc[j][3] = __expf(sc[j][3] - M1);
            s0 += sc[j][0] + sc[j][1];
            s1 += sc[j][2] + sc[j][3];
        }
        s0 += __shfl_xor_sync(~0u, s0, 1); s0 += __shfl_xor_sync(~0u, s0, 2);
        s1 += __shfl_xor_sync(~0u, s1, 1); s1 += __shfl_xor_sync(~0u, s1, 2);
        if (tig == 0) {
            ssum[r0 * 2 + snh] = s0;
            ssum[r1 * 2 + snh] = s1;
        }
    }
    __syncthreads();
    if (sa) {
        int r0 = sh * 16 + g, r1 = r0 + 8;
        float inv0 = 1.f / (ssum[r0 * 2] + ssum[r0 * 2 + 1]);
        float inv1 = 1.f / (ssum[r1 * 2] + ssum[r1 * 2 + 1]);
        #pragma unroll
        for (int j = 0; j < 4; j++) {
            int n0 = snh * 32 + j * 8;
            *(float2*)&P[r0 * P_STR + n0 + 2*tig] =
                make_float2(rtf(sc[j][0] * inv0), rtf(sc[j][1] * inv0));
            *(float2*)&P[r1 * P_STR + n0 + 2*tig] =
                make_float2(rtf(sc[j][2] * inv1), rtf(sc[j][3] * inv1));
        }
    }
    __syncthreads();

    // ---- GEMM-V: N=224, K=112 from Xs -> Vr ----
    {
        const unsigned* Xb = (const unsigned*)Xs;
        const unsigned* Wb = (const unsigned*)g_wbig;
        int nt = (warp < 4) ? 3 : 2;
        float acc[3][4][4];
        #pragma unroll
        for (int ti = 0; ti < 3; ti++) if (ti < nt) {
            int col = 448 + (warp + ti * 12) * 8;
            float bv0 = g_bbig[col + 2 * tig];
            float bv1 = g_bbig[col + 2 * tig + 1];
            #pragma unroll
            for (int mt = 0; mt < 4; mt++) {
                acc[ti][mt][0] = bv0; acc[ti][mt][1] = bv1;
                acc[ti][mt][2] = bv0; acc[ti][mt][3] = bv1;
            }
        }
        for (int kc = 0; kc < 112; kc += 8) {
            unsigned a[4][4];
            #pragma unroll
            for (int mt = 0; mt < 4; mt++) {
                int r0 = (mt * 16 + g) * XS_STR + kc;
                int r1 = r0 + 8 * XS_STR;
                a[mt][0] = Xb[r0 + tig];
                a[mt][1] = Xb[r1 + tig];
                a[mt][2] = Xb[r0 + tig + 4];
                a[mt][3] = Xb[r1 + tig + 4];
            }
            #pragma unroll
            for (int ti = 0; ti < 3; ti++) if (ti < nt) {
                int col = 448 + (warp + ti * 12) * 8 + g;
                unsigned b0 = Wb[(kc + tig) * 896 + col];
                unsigned b1 = Wb[(kc + tig + 4) * 896 + col];
                #pragma unroll
                for (int mt = 0; mt < 4; mt++)
                    mma_tf32(acc[ti][mt], a[mt][0], a[mt][1], a[mt][2], a[mt][3], b0, b1);
            }
        }
        #pragma unroll
        for (int ti = 0; ti < 3; ti++) if (ti < nt) {
            int dl = (warp + ti * 12) * 8 + 2 * tig;
            #pragma unroll
            for (int mt = 0; mt < 4; mt++) {
                int t0r = mt * 16 + g;
                *(float2*)&Vr[t0r * VR_STR + dl] =
                    make_float2(rtf(acc[ti][mt][0]), rtf(acc[ti][mt][1]));
                *(float2*)&Vr[(t0r + 8) * VR_STR + dl] =
                    make_float2(rtf(acc[ti][mt][2]), rtf(acc[ti][mt][3]));
            }
        }
    }
    __syncthreads();

    // ---- PV: O[q][d] per head -> Ot (aliases Xs) ----
    {
        const unsigned* Pb = (const unsigned*)P;
        const unsigned* Vb = (const unsigned*)Vr;
        int nt = (warp < 4) ? 3 : 2;
        float po[3][4];
        #pragma unroll
        for (int ti = 0; ti < 3; ti++)
            #pragma unroll
            for (int e = 0; e < 4; e++) po[ti][e] = 0.f;
        #pragma unroll
        for (int ti = 0; ti < 3; ti++) if (ti < nt) {
            int n0 = (warp + ti * 12) * 8;
            int h  = n0 / 56;
            #pragma unroll
            for (int kc = 0; kc < 64; kc += 8) {
                unsigned a0 = Pb[(h * 16 + g) * P_STR + kc + tig];
                unsigned a1 = Pb[(h * 16 + g + 8) * P_STR + kc + tig];
                unsigned a2 = Pb[(h * 16 + g) * P_STR + kc + tig + 4];
                unsigned a3 = Pb[(h * 16 + g + 8) * P_STR + kc + tig + 4];
                unsigned b0 = Vb[(kc + tig) * VR_STR + n0 + g];
                unsigned b1 = Vb[(kc + tig + 4) * VR_STR + n0 + g];
                mma_tf32(po[ti], a0, a1, a2, a3, b0, b1);
            }
        }
        #pragma unroll
        for (int ti = 0; ti < 3; ti++) if (ti < nt) {
            int n0 = (warp + ti * 12) * 8 + 2 * tig;
            *(float2*)&Ot[g * OT_STR + n0] = make_float2(rtf(po[ti][0]), rtf(po[ti][1]));
            *(float2*)&Ot[(g + 8) * OT_STR + n0] = make_float2(rtf(po[ti][2]), rtf(po[ti][3]));
        }
    }
    __syncthreads();

    // ---- attn_proj (16x224x224) + residual RMW into g_hs ----
    {
        const unsigned* Ob = (const unsigned*)Ot;
        int nt = (warp < 4) ? 3 : 2;
        float pa[3][4];
        #pragma unroll
        for (int ti = 0; ti < 3; ti++) if (ti < nt) {
            int col = (warp + ti * 12) * 8;
            float bv0 = bp[col + 2 * tig], bv1 = bp[col + 2 * tig + 1];
            pa[ti][0] = bv0; pa[ti][1] = bv1; pa[ti][2] = bv0; pa[ti][3] = bv1;
        }
        #pragma unroll 4
        for (int kc = 0; kc < 224; kc += 8) {
            unsigned a0 = Ob[g * OT_STR + kc + tig];
            unsigned a1 = Ob[(g + 8) * OT_STR + kc + tig];
            unsigned a2 = Ob[g * OT_STR + kc + tig + 4];
            unsigned a3 = Ob[(g + 8) * OT_STR + kc + tig + 4];
            #pragma unroll
            for (int ti = 0; ti < 3; ti++) if (ti < nt) {
                int n0 = (warp + ti * 12) * 8;
                unsigned b0 = __float_as_uint(g_wpt[(kc + tig) * 224 + n0 + g]);
                unsigned b1 = __float_as_uint(g_wpt[(kc + tig + 4) * 224 + n0 + g]);
                mma_tf32(pa[ti], a0, a1, a2, a3, b0, b1);
            }
        }
        int y20 = wy * 4 + (g >> 2),     x2 = wx * 4 + (g & 3);
        int y21 = y20 + 2;
        size_t base0 = (((size_t)b * 64 + y20) * 64 + x2) * 224;
        size_t base1 = (((size_t)b * 64 + y21) * 64 + x2) * 224;
        #pragma unroll
        for (int ti = 0; ti < 3; ti++) if (ti < nt) {
            int n0 = (warp + ti * 12) * 8 + 2 * tig;
            float2 h0 = *(float2*)&g_hs[base0 + n0];
            *(float2*)&g_hs[base0 + n0] =
                make_float2(h0.x + pa[ti][0], h0.y + pa[ti][1]);
            float2 h1 = *(float2*)&g_hs[base1 + n0];
            *(float2*)&g_hs[base1 + n0] =
                make_float2(h1.x + pa[ti][2], h1.y + pa[ti][3]);
        }
    }
}

// ---------------------------------------------------------------------------
// K4: out = hs + MLP(LN2(hs)); 512 blocks x 448 threads (unchanged)
// ---------------------------------------------------------------------------
#define XLN_STR 228
#define HA_STR  452
#define SMEM4   ((64 * XLN_STR + 64 * HA_STR) * 4)   // 174080 B

__global__ void __launch_bounds__(448) k_mlp(
        const float* __restrict__ g2, const float* __restrict__ b2,
        const float* __restrict__ b1, const float* __restrict__ b2m,
        float* __restrict__ out) {
    extern __shared__ float sm[];
    float* Xln = sm;
    float* Ha  = sm + 64 * XLN_STR;

    int t0   = blockIdx.x * 64;
    int tid  = threadIdx.x;
    int warp = tid >> 5, lane = tid & 31;
    int g = lane >> 2, tig = lane & 3;

    {
        float gv[7], bv[7];
        #pragma unroll
        for (int k = 0; k < 7; k++) { gv[k] = g2[lane + 32*k]; bv[k] = b2[lane + 32*k]; }
        for (int t = warp; t < 64; t += 14) {
            const float* hr = &g_hs[(size_t)(t0 + t) * 224];
            float v[7]; float s = 0.f;
            #pragma unroll
            for (int k = 0; k < 7; k++) { v[k] = hr[lane + 32*k]; s += v[k]; }
            #pragma unroll
            for (int o = 16; o; o >>= 1) s += __shfl_xor_sync(~0u, s, o);
            float m = s * (1.f / 224.f);
            float q = 0.f;
            #pragma unroll
            for (int k = 0; k < 7; k++) { v[k] -= m; q += v[k] * v[k]; }
            #pragma unroll
            for (int o = 16; o; o >>= 1) q += __shfl_xor_sync(~0u, q, o);
            float rs = rsqrtf(q * (1.f / 224.f) + 1e-6f);
            #pragma unroll
            for (int k = 0; k < 7; k++)
                Xln[t * XLN_STR + lane + 32*k] = rtf(v[k] * rs * gv[k] + bv[k]);
        }
    }
    __syncthreads();

    const unsigned* Xb = (const unsigned*)Xln;
    const unsigned* Hb = (const unsigned*)Ha;
    const unsigned* W1 = (const unsigned*)g_w1t;
    const unsigned* W2 = (const unsigned*)g_w2t;

    int n0w = warp * 16;
    float acc2[4][2][4];
    #pragma unroll
    for (int j = 0; j < 2; j++) {
        float bv0 = b2m[n0w + j * 8 + 2 * tig];
        float bv1 = b2m[n0w + j * 8 + 2 * tig + 1];
        #pragma unroll
        for (int mt = 0; mt < 4; mt++) {
            acc2[mt][j][0] = bv0; acc2[mt][j][1] = bv1;
            acc2[mt][j][2] = bv0; acc2[mt][j][3] = bv1;
        }
    }

    #pragma unroll 1
    for (int hp = 0; hp < 2; hp++) {
        int hb = hp * 448;
        {
            int cb = hb + warp * 32;
            float acc1[4][4][4];
            #pragma unroll
            for (int j = 0; j < 4; j++) {
                float bv0 = b1[cb + j * 8 + 2 * tig];
                float bv1 = b1[cb + j * 8 + 2 * tig + 1];
                #pragma unroll
                for (int mt = 0; mt < 4; mt++) {
                    acc1[mt][j][0] = bv0; acc1[mt][j][1] = bv1;
                    acc1[mt][j][2] = bv0; acc1[mt][j][3] = bv1;
                }
            }
            for (int kc = 0; kc < 224; kc += 8) {
                unsigned a[4][4];
                #pragma unroll
                for (int mt = 0; mt < 4; mt++) {
                    int r0 = (mt * 16 + g) * XLN_STR + kc;
                    int r1 = r0 + 8 * XLN_STR;
                    a[mt][0] = Xb[r0 + tig];
                    a[mt][1] = Xb[r1 + tig];
                    a[mt][2] = Xb[r0 + tig + 4];
                    a[mt][3] = Xb[r1 + tig + 4];
                }
                #pragma unroll
                for (int j = 0; j < 4; j++) {
                    int col = cb + j * 8 + g;
                    unsigned w0 = W1[(kc + tig) * 896 + col];
                    unsigned w1 = W1[(kc + tig + 4) * 896 + col];
                    #pragma unroll
                    for (int mt = 0; mt < 4; mt++)
                        mma_tf32(acc1[mt][j], a[mt][0], a[mt][1], a[mt][2], a[mt][3], w0, w1);
                }
            }
            int lb = warp * 32;
            #pragma unroll
            for (int mt = 0; mt < 4; mt++)
                #pragma unroll
                for (int j = 0; j < 4; j++) {
                    int lh = lb + j * 8 + 2 * tig;
                    int m0 = mt * 16 + g;
                    float a0 = acc1[mt][j][0], a1 = acc1[mt][j][1];
                    float a2 = acc1[mt][j][2], a3 = acc1[mt][j][3];
                    *(float2*)&Ha[m0 * HA_STR + lh] = make_float2(
                        rtf(0.5f * a0 * (1.f + erff(a0 * 0.70710678118654752f))),
                        rtf(0.5f * a1 * (1.f + erff(a1 * 0.70710678118654752f))));
                    *(float2*)&Ha[(m0 + 8) * HA_STR + lh] = make_float2(
                        rtf(0.5f * a2 * (1.f + erff(a2 * 0.70710678118654752f))),
                        rtf(0.5f * a3 * (1.f + erff(a3 * 0.70710678118654752f))));
                }
        }
        __syncthreads();
        for (int kc = 0; kc < 448; kc += 8) {
            unsigned a[4][4];
            #pragma unroll
            for (int mt = 0; mt < 4; mt++) {
                int r0 = (mt * 16 + g) * HA_STR + kc;
                int r1 = r0 + 8 * HA_STR;
                a[mt][0] = Hb[r0 + tig];
                a[mt][1] = Hb[r1 + tig];
                a[mt][2] = Hb[r0 + tig + 4];
                a[mt][3] = Hb[r1 + tig + 4];
            }
            #pragma unroll
            for (int j = 0; j < 2; j++) {
                int col = n0w + j * 8 + g;
                unsigned w0 = W2[(hb + kc + tig) * 224 + col];
                unsigned w1 = W2[(hb + kc + tig + 4) * 224 + col];
                #pragma unroll
                for (int mt = 0; mt < 4; mt++)
                    mma_tf32(acc2[mt][j], a[mt][0], a[mt][1], a[mt][2], a[mt][3], w0, w1);
            }
        }
        __syncthreads();
    }

    #pragma unroll
    for (int mt = 0; mt < 4; mt++)
        #pragma unroll
        for (int j = 0; j < 2; j++) {
            int n = n0w + j * 8 + 2 * tig;
            int m0 = t0 + mt * 16 + g;
            float2 h0 = *(const float2*)&g_hs[(size_t)m0 * 224 + n];
            *(float2*)&out[(size_t)m0 * 224 + n] =
                make_float2(h0.x + acc2[mt][j][0], h0.y + acc2[mt][j][1]);
            float2 h1 = *(const float2*)&g_hs[(size_t)(m0 + 8) * 224 + n];
            *(float2*)&out[(size_t)(m0 + 8) * 224 + n] =
                make_float2(h1.x + acc2[mt][j][2], h1.y + acc2[mt][j][3]);
        }
}

// ---------------------------------------------------------------------------
extern "C" void kernel_launch(void* const* d_in, const int* in_sizes, int n_in,
                              void* d_out, int out_size) {
    const float* hidden   = (const float*)d_in[0];
    const float* ln1_g    = (const float*)d_in[1];
    const float* ln1_b    = (const float*)d_in[2];
    const float* qkv_w    = (const float*)d_in[3];
    const float* qkv_b    = (const float*)d_in[4];
    const float* aproj_w  = (const float*)d_in[5];
    const float* aproj_b  = (const float*)d_in[6];
    const float* rproj_w  = (const float*)d_in[7];
    const float* rproj_b  = (const float*)d_in[8];
    const float* ln2_g    = (const float*)d_in[9];
    const float* ln2_b    = (const float*)d_in[10];
    const float* mlp1_w   = (const float*)d_in[11];
    const float* mlp1_b   = (const float*)d_in[12];
    const float* mlp2_w   = (const float*)d_in[13];
    const float* mlp2_b   = (const float*)d_in[14];
    float* out = (float*)d_out;

    cudaFuncSetAttribute(k_attn, cudaFuncAttributeMaxDynamicSharedMemorySize, SMEM3);
    cudaFuncSetAttribute(k_mlp,  cudaFuncAttributeMaxDynamicSharedMemorySize, SMEM4);

    k_prep<<<196, 1024>>>(mlp1_w, mlp2_w, qkv_w, rproj_w, aproj_w, qkv_b, rproj_b);
    k_attn<<<2048, 384, SMEM3>>>(hidden, ln1_g, ln1_b, aproj_b);
    k_mlp<<<512, 448, SMEM4>>>(ln2_g, ln2_b, mlp1_b, mlp2_b, out);
}

// round 8
// speedup vs baseline: 1.2854x; 1.2854x over previous
#include <cuda_runtime.h>
#include <math.h>

#define NTOK  (8*64*64)

// Scratch (device globals)
__device__ float g_hs[(size_t)NTOK * 224];   // residual + attn output
__device__ float g_w1t[224 * 896];           // tf32 mlp1_w
__device__ float g_w2t[896 * 224];           // tf32 mlp2_w
__device__ float g_wbig[112 * 896];          // tf32 [qkv_w | res_proj_w]
__device__ float g_wpt[224 * 224];           // tf32 attn_proj_w
__device__ float g_bbig[896];                // [qkv_b | res_proj_b]

__device__ __forceinline__ unsigned f2tf32(float x) {
    unsigned r;
    asm("cvt.rna.tf32.f32 %0, %1;" : "=r"(r) : "f"(x));
    return r;
}
__device__ __forceinline__ float rtf(float x) { return __uint_as_float(f2tf32(x)); }

__device__ __forceinline__ void mma_tf32(float* c,
        unsigned a0, unsigned a1, unsigned a2, unsigned a3,
        unsigned b0, unsigned b1) {
    asm("mma.sync.aligned.m16n8k8.row.col.f32.tf32.tf32.f32 "
        "{%0,%1,%2,%3}, {%4,%5,%6,%7}, {%8,%9}, {%0,%1,%2,%3};"
        : "+f"(c[0]), "+f"(c[1]), "+f"(c[2]), "+f"(c[3])
        : "r"(a0), "r"(a1), "r"(a2), "r"(a3), "r"(b0), "r"(b1));
}

// ---------------------------------------------------------------------------
// K0: round weights to tf32, build combined [qkv|res] weight + bias
// ---------------------------------------------------------------------------
__global__ void k_prep(const float* __restrict__ W1,   const float* __restrict__ W2,
                       const float* __restrict__ Wqkv, const float* __restrict__ Wrp,
                       const float* __restrict__ Wp,
                       const float* __restrict__ bqkv, const float* __restrict__ brp) {
    int i = blockIdx.x * 1024 + threadIdx.x;
    if (i < 224 * 896) { g_w1t[i] = rtf(W1[i]); g_w2t[i] = rtf(W2[i]); }
    if (i < 112 * 896) {
        int r = i / 896, c = i - r * 896;
        float v = (c < 672) ? Wqkv[r * 672 + c] : Wrp[r * 224 + (c - 672)];
        g_wbig[i] = rtf(v);
    }
    if (i < 224 * 224) g_wpt[i] = rtf(Wp[i]);
    if (i < 896) g_bbig[i] = (i < 672) ? bqkv[i] : brp[i - 672];
}

// ---------------------------------------------------------------------------
// K3: fused LN1 + QKV/R GEMM + pooling + attention + proj + residual
// 2048 blocks x 448 threads (14 warps)  [round-6 structure]
// smem: Xs[64][116] | Kt[224][72] | Vrow[64][232] | Qt[16][236] | Rt[16][236]
//       | stats 256
// P (64x76) aliases Xs; Ot (16x236) aliases Qt.
// ---------------------------------------------------------------------------
#define XS_STR 116
#define KT_STR 72
#define VR_STR 232
#define QT_STR 236
#define RT_STR 236
#define OT_STR 236
#define P_STR  76
#define XS_N (64 * XS_STR)     // 7424
#define KT_N (224 * KT_STR)    // 16128
#define VR_N (64 * VR_STR)     // 14848
#define QT_N (16 * QT_STR)     // 3776
#define RT_N (16 * RT_STR)     // 3776
#define SMEM3 ((XS_N + KT_N + VR_N + QT_N + RT_N + 256) * 4)   // 184832 B

__global__ void __launch_bounds__(448) k_attn(
        const float* __restrict__ hidden,
        const float* __restrict__ ln1g, const float* __restrict__ ln1b,
        const float* __restrict__ bp) {
    extern __shared__ float sm[];
    float* Xs   = sm;
    float* Kt   = Xs + XS_N;
    float* Vrow = Kt + KT_N;
    float* Qt   = Vrow + VR_N;
    float* Rt   = Qt + QT_N;
    float* smax = Rt + RT_N;      // [64][2]
    float* ssum = smax + 128;     // [64][2]
    float* P    = Xs;    // alias (X dead after QKV)
    float* Ot   = Qt;    // alias (Qt dead after scores)

    int wi = blockIdx.x;
    int b  = wi >> 8;
    int r  = wi & 255;
    int wy = r >> 4, wx = r & 15;
    int tid  = threadIdx.x;
    int warp = tid >> 5, lane = tid & 31;
    int g = lane >> 2, tig = lane & 3;

    // ---- stage raw window ----
    for (int e = tid; e < 64 * 28; e += 448) {
        int t = e / 28, c4 = (e - t * 28) * 4;
        int y = wy * 8 + (t >> 3), x = wx * 8 + (t & 7);
        *(float4*)&Xs[t * XS_STR + c4] =
            *(const float4*)&hidden[(((size_t)b * 128 + y) * 128 + x) * 112 + c4];
    }
    __syncthreads();

    // ---- LN1 in place (warp per token), tf32-rounded ----
    {
        float gg0 = ln1g[lane], gg1 = ln1g[lane + 32], gg2 = ln1g[lane + 64];
        float bb0 = ln1b[lane], bb1 = ln1b[lane + 32], bb2 = ln1b[lane + 64];
        float gg3 = 0.f, bb3 = 0.f;
        if (lane < 16) { gg3 = ln1g[lane + 96]; bb3 = ln1b[lane + 96]; }
        for (int t = warp; t < 64; t += 14) {
            float* row = Xs + t * XS_STR;
            float v0 = row[lane], v1 = row[lane + 32], v2 = row[lane + 64];
            float v3 = (lane < 16) ? row[lane + 96] : 0.f;
            float s = v0 + v1 + v2 + v3;
            #pragma unroll
            for (int o = 16; o; o >>= 1) s += __shfl_xor_sync(~0u, s, o);
            float m = s * (1.f / 112.f);
            float d0 = v0 - m, d1 = v1 - m, d2 = v2 - m;
            float d3 = (lane < 16) ? v3 - m : 0.f;
            float q = d0*d0 + d1*d1 + d2*d2 + d3*d3;
            #pragma unroll
            for (int o = 16; o; o >>= 1) q += __shfl_xor_sync(~0u, q, o);
            float rs = rsqrtf(q * (1.f / 112.f) + 1e-6f);
            row[lane]      = rtf(d0 * rs * gg0 + bb0);
            row[lane + 32] = rtf(d1 * rs * gg1 + bb1);
            row[lane + 64] = rtf(d2 * rs * gg2 + bb2);
            if (lane < 16) row[lane + 96] = rtf(d3 * rs * gg3 + bb3);
        }
    }
    __syncthreads();

    // ---- QKV+R GEMM: M=64, N=896, K=112; warp n-slice 64, two j-passes of 4 ----
    {
        const unsigned* Xb = (const unsigned*)Xs;
        const unsigned* Wb = (const unsigned*)g_wbig;
        #pragma unroll
        for (int pass = 0; pass < 2; pass++) {
            int colbase = warp * 64 + pass * 32;
            float acc[4][4][4];
            #pragma unroll
            for (int j = 0; j < 4; j++) {
                int col = colbase + j * 8;
                float bv0 = g_bbig[col + 2 * tig];
                float bv1 = g_bbig[col + 2 * tig + 1];
                #pragma unroll
                for (int mt = 0; mt < 4; mt++) {
                    acc[mt][j][0] = bv0; acc[mt][j][1] = bv1;
                    acc[mt][j][2] = bv0; acc[mt][j][3] = bv1;
                }
            }
            for (int kc = 0; kc < 112; kc += 8) {
                unsigned a[4][4];
                #pragma unroll
                for (int mt = 0; mt < 4; mt++) {
                    int r0 = (mt * 16 + g) * XS_STR + kc;
                    int r1 = r0 + 8 * XS_STR;
                    a[mt][0] = Xb[r0 + tig];
                    a[mt][1] = Xb[r1 + tig];
                    a[mt][2] = Xb[r0 + tig + 4];
                    a[mt][3] = Xb[r1 + tig + 4];
                }
                #pragma unroll
                for (int j = 0; j < 4; j++) {
                    int col = colbase + j * 8 + g;
                    unsigned b0 = Wb[(kc + tig) * 896 + col];
                    unsigned b1 = Wb[(kc + tig + 4) * 896 + col];
                    #pragma unroll
                    for (int mt = 0; mt < 4; mt++)
                        mma_tf32(acc[mt][j], a[mt][0], a[mt][1], a[mt][2], a[mt][3], b0, b1);
                }
            }
            // routed stores (uniform branch per warp/j)
            #pragma unroll
            for (int j = 0; j < 4; j++) {
                int col = colbase + j * 8;
                int mat = col / 224;
                int lc  = col - mat * 224;
                if (mat == 1) {            // K -> Kt[d][t]  (scalar: transpose)
                    #pragma unroll
                    for (int mt = 0; mt < 4; mt++) {
                        int t0r = mt * 16 + g;
                        Kt[(lc + 2*tig)     * KT_STR + t0r]     = rtf(acc[mt][j][0]);
                        Kt[(lc + 2*tig + 1) * KT_STR + t0r]     = rtf(acc[mt][j][1]);
                        Kt[(lc + 2*tig)     * KT_STR + t0r + 8] = rtf(acc[mt][j][2]);
                        Kt[(lc + 2*tig + 1) * KT_STR + t0r + 8] = rtf(acc[mt][j][3]);
                    }
                } else if (mat == 2) {     // V -> Vrow[t][d]  (float2)
                    #pragma unroll
                    for (int mt = 0; mt < 4; mt++) {
                        int t0r = mt * 16 + g;
                        *(float2*)&Vrow[t0r * VR_STR + lc + 2*tig] =
                            make_float2(rtf(acc[mt][j][0]), rtf(acc[mt][j][1]));
                        *(float2*)&Vrow[(t0r + 8) * VR_STR + lc + 2*tig] =
                            make_float2(rtf(acc[mt][j][2]), rtf(acc[mt][j][3]));
                    }
                } else {                   // Q (mat 0) or R (mat 3): 2x2 pool in regs
                    #pragma unroll
                    for (int mt = 0; mt < 4; mt++) {
                        float m0 = fmaxf(acc[mt][j][0], acc[mt][j][2]);  // rows g, g+8
                        float m1 = fmaxf(acc[mt][j][1], acc[mt][j][3]);
                        m0 = fmaxf(m0, __shfl_xor_sync(~0u, m0, 4));     // lanes g ^ 1
                        m1 = fmaxf(m1, __shfl_xor_sync(~0u, m1, 4));
                        if (!(g & 1)) {
                            int q = mt * 4 + (g >> 1);
                            if (mat == 0)
                                *(float2*)&Qt[q * QT_STR + lc + 2*tig] =
                                    make_float2(rtf(m0), rtf(m1));
                            else
                                *(float2*)&Rt[q * RT_STR + lc + 2*tig] =
                                    make_float2(m0, m1);
                        }
                    }
                }
            }
        }
    }
    __syncthreads();

    // ---- scores + in-register softmax (8 warps) -> P (aliases Xs) ----
    const float scale = 0.13363062095621219f;   // 56^-0.5
    bool sa = (warp < 8);
    int sh = warp >> 1, snh = warp & 1;
    float sc[4][4];
    if (sa) {
        const unsigned* Qb = (const unsigned*)Qt;
        const unsigned* Kb = (const unsigned*)Kt;
        #pragma unroll
        for (int j = 0; j < 4; j++)
            #pragma unroll
            for (int e = 0; e < 4; e++) sc[j][e] = 0.f;
        #pragma unroll
        for (int kc = 0; kc < 56; kc += 8) {
            int kd = sh * 56 + kc;
            unsigned a0 = Qb[g * QT_STR + kd + tig];
            unsigned a1 = Qb[(g + 8) * QT_STR + kd + tig];
            unsigned a2 = Qb[g * QT_STR + kd + tig + 4];
            unsigned a3 = Qb[(g + 8) * QT_STR + kd + tig + 4];
            #pragma unroll
            for (int j = 0; j < 4; j++) {
                int n0 = snh * 32 + j * 8;
                unsigned b0 = Kb[(kd + tig) * KT_STR + n0 + g];
                unsigned b1 = Kb[(kd + tig + 4) * KT_STR + n0 + g];
                mma_tf32(sc[j], a0, a1, a2, a3, b0, b1);
            }
        }
        // per-warp (half-row) max via quad shuffles
        float m0 = -1e30f, m1 = -1e30f;
        #pragma unroll
        for (int j = 0; j < 4; j++) {
            sc[j][0] *= scale; sc[j][1] *= scale;
            sc[j][2] *= scale; sc[j][3] *= scale;
            m0 = fmaxf(m0, fmaxf(sc[j][0], sc[j][1]));
            m1 = fmaxf(m1, fmaxf(sc[j][2], sc[j][3]));
        }
        m0 = fmaxf(m0, __shfl_xor_sync(~0u, m0, 1));
        m0 = fmaxf(m0, __shfl_xor_sync(~0u, m0, 2));
        m1 = fmaxf(m1, __shfl_xor_sync(~0u, m1, 1));
        m1 = fmaxf(m1, __shfl_xor_sync(~0u, m1, 2));
        if (tig == 0) {
            smax[(sh * 16 + g) * 2 + snh]     = m0;
            smax[(sh * 16 + g + 8) * 2 + snh] = m1;
        }
    }
    __syncthreads();
    if (sa) {
        int r0 = sh * 16 + g, r1 = r0 + 8;
        float M0 = fmaxf(smax[r0 * 2], smax[r0 * 2 + 1]);
        float M1 = fmaxf(smax[r1 * 2], smax[r1 * 2 + 1]);
        float s0 = 0.f, s1 = 0.f;
        #pragma unroll
        for (int j = 0; j < 4; j++) {
            sc[j][0] = __expf(sc[j][0] - M0); sc[j][1] = __expf(sc[j][1] - M0);
            sc[j][2] = __expf(sc[j][2] - M1); sc[j][3] = __expf(sc[j][3] - M1);
            s0 += sc[j][0] + sc[j][1];
            s1 += sc[j][2] + sc[j][3];
        }
        s0 += __shfl_xor_sync(~0u, s0, 1); s0 += __shfl_xor_sync(~0u, s0, 2);
        s1 += __shfl_xor_sync(~0u, s1, 1); s1 += __shfl_xor_sync(~0u, s1, 2);
        if (tig == 0) {
            ssum[r0 * 2 + snh] = s0;
            ssum[r1 * 2 + snh] = s1;
        }
    }
    __syncthreads();
    if (sa) {
        int r0 = sh * 16 + g, r1 = r0 + 8;
        float inv0 = 1.f / (ssum[r0 * 2] + ssum[r0 * 2 + 1]);
        float inv1 = 1.f / (ssum[r1 * 2] + ssum[r1 * 2 + 1]);
        #pragma unroll
        for (int j = 0; j < 4; j++) {
            int n0 = snh * 32 + j * 8;
            *(float2*)&P[r0 * P_STR + n0 + 2*tig] =
                make_float2(rtf(sc[j][0] * inv0), rtf(sc[j][1] * inv0));
            *(float2*)&P[r1 * P_STR + n0 + 2*tig] =
                make_float2(rtf(sc[j][2] * inv1), rtf(sc[j][3] * inv1));
        }
    }
    __syncthreads();

    // ---- PV: per head 16x56x64 -> Ot (aliases Qt) ----
    {
        const unsigned* Pb = (const unsigned*)P;
        const unsigned* Vb = (const unsigned*)Vrow;
        #pragma unroll
        for (int ui = 0; ui < 2; ui++) {
            int u = warp * 2 + ui;        // 0..27
            int h = u / 7, j = u - h * 7;
            int n0 = h * 56 + j * 8;
            float acc[4] = {0.f, 0.f, 0.f, 0.f};
            #pragma unroll
            for (int kc = 0; kc < 64; kc += 8) {
                unsigned a0 = Pb[(h * 16 + g) * P_STR + kc + tig];
                unsigned a1 = Pb[(h * 16 + g + 8) * P_STR + kc + tig];
                unsigned a2 = Pb[(h * 16 + g) * P_STR + kc + tig + 4];
                unsigned a3 = Pb[(h * 16 + g + 8) * P_STR + kc + tig + 4];
                unsigned b0 = Vb[(kc + tig) * VR_STR + n0 + g];
                unsigned b1 = Vb[(kc + tig + 4) * VR_STR + n0 + g];
                mma_tf32(acc, a0, a1, a2, a3, b0, b1);
            }
            *(float2*)&Ot[g * OT_STR + n0 + 2*tig] =
                make_float2(rtf(acc[0]), rtf(acc[1]));
            *(float2*)&Ot[(g + 8) * OT_STR + n0 + 2*tig] =
                make_float2(rtf(acc[2]), rtf(acc[3]));
        }
    }
    __syncthreads();

    // ---- attn_proj (16x224x224), accumulate into Rt ----
    {
        const unsigned* Ob = (const unsigned*)Ot;
        int n0w = warp * 16;
        float acc[2][4];
        #pragma unroll
        for (int j = 0; j < 2; j++) {
            int col = n0w + j * 8;
            float bv0 = bp[col + 2 * tig];
            float bv1 = bp[col + 2 * tig + 1];
            acc[j][0] = bv0; acc[j][1] = bv1; acc[j][2] = bv0; acc[j][3] = bv1;
        }
        #pragma unroll 4
        for (int kc = 0; kc < 224; kc += 8) {
            unsigned a0 = Ob[g * OT_STR + kc + tig];
            unsigned a1 = Ob[(g + 8) * OT_STR + kc + tig];
            unsigned a2 = Ob[g * OT_STR + kc + tig + 4];
            unsigned a3 = Ob[(g + 8) * OT_STR + kc + tig + 4];
            #pragma unroll
            for (int j = 0; j < 2; j++) {
                int n0 = n0w + j * 8;
                unsigned b0 = __float_as_uint(g_wpt[(kc + tig) * 224 + n0 + g]);
                unsigned b1 = __float_as_uint(g_wpt[(kc + tig + 4) * 224 + n0 + g]);
                mma_tf32(acc[j], a0, a1, a2, a3, b0, b1);
            }
        }
        #pragma unroll
        for (int j = 0; j < 2; j++) {
            int d = n0w + j * 8 + 2 * tig;
            float2 r0v = *(float2*)&Rt[g * RT_STR + d];
            *(float2*)&Rt[g * RT_STR + d] =
                make_float2(r0v.x + acc[j][0], r0v.y + acc[j][1]);
            float2 r1v = *(float2*)&Rt[(g + 8) * RT_STR + d];
            *(float2*)&Rt[(g + 8) * RT_STR + d] =
                make_float2(r1v.x + acc[j][2], r1v.y + acc[j][3]);
        }
    }
    __syncthreads();

    // ---- coalesced writeout of hs = residual + proj ----
    for (int e = tid; e < 16 * 56; e += 448) {
        int q = e / 56, c4 = (e - q * 56) * 4;
        int y2 = wy * 4 + (q >> 2), x2 = wx * 4 + (q & 3);
        *(float4*)&g_hs[(((size_t)b * 64 + y2) * 64 + x2) * 224 + c4] =
            *(float4*)&Rt[q * RT_STR + c4];
    }
}

// ---------------------------------------------------------------------------
// K4: out = hs + MLP(LN2(hs)); 512 blocks x 448 threads (round-6, unchanged)
// ---------------------------------------------------------------------------
#define XLN_STR 228
#define HA_STR  452
#define SMEM4   ((64 * XLN_STR + 64 * HA_STR) * 4)   // 174080 B

__global__ void __launch_bounds__(448) k_mlp(
        const float* __restrict__ g2, const float* __restrict__ b2,
        const float* __restrict__ b1, const float* __restrict__ b2m,
        float* __restrict__ out) {
    extern __shared__ float sm[];
    float* Xln = sm;
    float* Ha  = sm + 64 * XLN_STR;

    int t0   = blockIdx.x * 64;
    int tid  = threadIdx.x;
    int warp = tid >> 5, lane = tid & 31;
    int g = lane >> 2, tig = lane & 3;

    {
        float gv[7], bv[7];
        #pragma unroll
        for (int k = 0; k < 7; k++) { gv[k] = g2[lane + 32*k]; bv[k] = b2[lane + 32*k]; }
        for (int t = warp; t < 64; t += 14) {
            const float* hr = &g_hs[(size_t)(t0 + t) * 224];
            float v[7]; float s = 0.f;
            #pragma unroll
            for (int k = 0; k < 7; k++) { v[k] = hr[lane + 32*k]; s += v[k]; }
            #pragma unroll
            for (int o = 16; o; o >>= 1) s += __shfl_xor_sync(~0u, s, o);
            float m = s * (1.f / 224.f);
            float q = 0.f;
            #pragma unroll
            for (int k = 0; k < 7; k++) { v[k] -= m; q += v[k] * v[k]; }
            #pragma unroll
            for (int o = 16; o; o >>= 1) q += __shfl_xor_sync(~0u, q, o);
            float rs = rsqrtf(q * (1.f / 224.f) + 1e-6f);
            #pragma unroll
            for (int k = 0; k < 7; k++)
                Xln[t * XLN_STR + lane + 32*k] = rtf(v[k] * rs * gv[k] + bv[k]);
        }
    }
    __syncthreads();

    const unsigned* Xb = (const unsigned*)Xln;
    const unsigned* Hb = (const unsigned*)Ha;
    const unsigned* W1 = (const unsigned*)g_w1t;
    const unsigned* W2 = (const unsigned*)g_w2t;

    int n0w = warp * 16;
    float acc2[4][2][4];
    #pragma unroll
    for (int j = 0; j < 2; j++) {
        float bv0 = b2m[n0w + j * 8 + 2 * tig];
        float bv1 = b2m[n0w + j * 8 + 2 * tig + 1];
        #pragma unroll
        for (int mt = 0; mt < 4; mt++) {
            acc2[mt][j][0] = bv0; acc2[mt][j][1] = bv1;
            acc2[mt][j][2] = bv0; acc2[mt][j][3] = bv1;
        }
    }

    #pragma unroll 1
    for (int hp = 0; hp < 2; hp++) {
        int hb = hp * 448;
        {
            int cb = hb + warp * 32;
            float acc1[4][4][4];
            #pragma unroll
            for (int j = 0; j < 4; j++) {
                float bv0 = b1[cb + j * 8 + 2 * tig];
                float bv1 = b1[cb + j * 8 + 2 * tig + 1];
                #pragma unroll
                for (int mt = 0; mt < 4; mt++) {
                    acc1[mt][j][0] = bv0; acc1[mt][j][1] = bv1;
                    acc1[mt][j][2] = bv0; acc1[mt][j][3] = bv1;
                }
            }
            for (int kc = 0; kc < 224; kc += 8) {
                unsigned a[4][4];
                #pragma unroll
                for (int mt = 0; mt < 4; mt++) {
                    int r0 = (mt * 16 + g) * XLN_STR + kc;
                    int r1 = r0 + 8 * XLN_STR;
                    a[mt][0] = Xb[r0 + tig];
                    a[mt][1] = Xb[r1 + tig];
                    a[mt][2] = Xb[r0 + tig + 4];
                    a[mt][3] = Xb[r1 + tig + 4];
                }
                #pragma unroll
                for (int j = 0; j < 4; j++) {
                    int col = cb + j * 8 + g;
                    unsigned w0 = W1[(kc + tig) * 896 + col];
                    unsigned w1 = W1[(kc + tig + 4) * 896 + col];
                    #pragma unroll
                    for (int mt = 0; mt < 4; mt++)
                        mma_tf32(acc1[mt][j], a[mt][0], a[mt][1], a[mt][2], a[mt][3], w0, w1);
                }
            }
            int lb = warp * 32;
            #pragma unroll
            for (int mt = 0; mt < 4; mt++)
                #pragma unroll
                for (int j = 0; j < 4; j++) {
                    int lh = lb + j * 8 + 2 * tig;
                    int m0 = mt * 16 + g;
                    float a0 = acc1[mt][j][0], a1 = acc1[mt][j][1];
                    float a2 = acc1[mt][j][2], a3 = acc1[mt][j][3];
                    *(float2*)&Ha[m0 * HA_STR + lh] = make_float2(
                        rtf(0.5f * a0 * (1.f + erff(a0 * 0.70710678118654752f))),
                        rtf(0.5f * a1 * (1.f + erff(a1 * 0.70710678118654752f))));
                    *(float2*)&Ha[(m0 + 8) * HA_STR + lh] = make_float2(
                        rtf(0.5f * a2 * (1.f + erff(a2 * 0.70710678118654752f))),
                        rtf(0.5f * a3 * (1.f + erff(a3 * 0.70710678118654752f))));
                }
        }
        __syncthreads();
        for (int kc = 0; kc < 448; kc += 8) {
            unsigned a[4][4];
            #pragma unroll
            for (int mt = 0; mt < 4; mt++) {
                int r0 = (mt * 16 + g) * HA_STR + kc;
                int r1 = r0 + 8 * HA_STR;
                a[mt][0] = Hb[r0 + tig];
                a[mt][1] = Hb[r1 + tig];
                a[mt][2] = Hb[r0 + tig + 4];
                a[mt][3] = Hb[r1 + tig + 4];
            }
            #pragma unroll
            for (int j = 0; j < 2; j++) {
                int col = n0w + j * 8 + g;
                unsigned w0 = W2[(hb + kc + tig) * 224 + col];
                unsigned w1 = W2[(hb + kc + tig + 4) * 224 + col];
                #pragma unroll
                for (int mt = 0; mt < 4; mt++)
                    mma_tf32(acc2[mt][j], a[mt][0], a[mt][1], a[mt][2], a[mt][3], w0, w1);
            }
        }
        __syncthreads();
    }

    #pragma unroll
    for (int mt = 0; mt < 4; mt++)
        #pragma unroll
        for (int j = 0; j < 2; j++) {
            int n = n0w + j * 8 + 2 * tig;
            int m0 = t0 + mt * 16 + g;
            float2 h0 = *(const float2*)&g_hs[(size_t)m0 * 224 + n];
            *(float2*)&out[(size_t)m0 * 224 + n] =
                make_float2(h0.x + acc2[mt][j][0], h0.y + acc2[mt][j][1]);
            float2 h1 = *(const float2*)&g_hs[(size_t)(m0 + 8) * 224 + n];
            *(float2*)&out[(size_t)(m0 + 8) * 224 + n] =
                make_float2(h1.x + acc2[mt][j][2], h1.y + acc2[mt][j][3]);
        }
}

// ---------------------------------------------------------------------------
extern "C" void kernel_launch(void* const* d_in, const int* in_sizes, int n_in,
                              void* d_out, int out_size) {
    const float* hidden   = (const float*)d_in[0];
    const float* ln1_g    = (const float*)d_in[1];
    const float* ln1_b    = (const float*)d_in[2];
    const float* qkv_w    = (const float*)d_in[3];
    const float* qkv_b    = (const float*)d_in[4];
    const float* aproj_w  = (const float*)d_in[5];
    const float* aproj_b  = (const float*)d_in[6];
    const float* rproj_w  = (const float*)d_in[7];
    const float* rproj_b  = (const float*)d_in[8];
    const float* ln2_g    = (const float*)d_in[9];
    const float* ln2_b    = (const float*)d_in[10];
    const float* mlp1_w   = (const float*)d_in[11];
    const float* mlp1_b   = (const float*)d_in[12];
    const float* mlp2_w   = (const float*)d_in[13];
    const float* mlp2_b   = (const float*)d_in[14];
    float* out = (float*)d_out;

    cudaFuncSetAttribute(k_attn, cudaFuncAttributeMaxDynamicSharedMemorySize, SMEM3);
    cudaFuncSetAttribute(k_mlp,  cudaFuncAttributeMaxDynamicSharedMemorySize, SMEM4);

    k_prep<<<196, 1024>>>(mlp1_w, mlp2_w, qkv_w, rproj_w, aproj_w, qkv_b, rproj_b);
    k_attn<<<2048, 448, SMEM3>>>(hidden, ln1_g, ln1_b, aproj_b);
    k_mlp<<<512, 448, SMEM4>>>(ln2_g, ln2_b, mlp1_b, mlp2_b, out);
}

// round 11
// speedup vs baseline: 1.2909x; 1.0043x over previous
#include <cuda_runtime.h>
#include <math.h>
#include <stdint.h>

#define NTOK  (8*64*64)

// Scratch (device globals)
__device__ float g_hs[(size_t)NTOK * 224];   // residual + attn output
__device__ float g_w1t[224 * 896];           // tf32 mlp1_w
__device__ float g_w2t[896 * 224];           // tf32 mlp2_w
__device__ float g_wbig[112 * 896];          // tf32 [qkv_w | res_proj_w]
__device__ float g_wpt[224 * 224];           // tf32 attn_proj_w
__device__ float g_bbig[896];                // [qkv_b | res_proj_b]

__device__ __forceinline__ unsigned f2tf32(float x) {
    unsigned r;
    asm("cvt.rna.tf32.f32 %0, %1;" : "=r"(r) : "f"(x));
    return r;
}
__device__ __forceinline__ float rtf(float x) { return __uint_as_float(f2tf32(x)); }

__device__ __forceinline__ void mma_tf32(float* c,
        unsigned a0, unsigned a1, unsigned a2, unsigned a3,
        unsigned b0, unsigned b1) {
    asm("mma.sync.aligned.m16n8k8.row.col.f32.tf32.tf32.f32 "
        "{%0,%1,%2,%3}, {%4,%5,%6,%7}, {%8,%9}, {%0,%1,%2,%3};"
        : "+f"(c[0]), "+f"(c[1]), "+f"(c[2]), "+f"(c[3])
        : "r"(a0), "r"(a1), "r"(a2), "r"(a3), "r"(b0), "r"(b1));
}

// ---------------------------------------------------------------------------
// K0: round weights to tf32, build combined [qkv|res] weight + bias
// ---------------------------------------------------------------------------
__global__ void k_prep(const float* __restrict__ W1,   const float* __restrict__ W2,
                       const float* __restrict__ Wqkv, const float* __restrict__ Wrp,
                       const float* __restrict__ Wp,
                       const float* __restrict__ bqkv, const float* __restrict__ brp) {
    int i = blockIdx.x * 1024 + threadIdx.x;
    if (i < 224 * 896) { g_w1t[i] = rtf(W1[i]); g_w2t[i] = rtf(W2[i]); }
    if (i < 112 * 896) {
        int r = i / 896, c = i - r * 896;
        float v = (c < 672) ? Wqkv[r * 672 + c] : Wrp[r * 224 + (c - 672)];
        g_wbig[i] = rtf(v);
    }
    if (i < 224 * 224) g_wpt[i] = rtf(Wp[i]);
    if (i < 896) g_bbig[i] = (i < 672) ? bqkv[i] : brp[i - 672];
}

// ---------------------------------------------------------------------------
// K3: fused LN1 + QKV/R GEMM + pooling + attention + proj + residual
// 2048 blocks x 448 threads (14 warps)
// smem: Xs[64][116] | Krow[64][236] | Vrow[64][232] | Qt[16][236] | Rt[16][236]
//       | stats 256
// P (64x76) aliases Xs; Ot (16x236) aliases Qt.
// ---------------------------------------------------------------------------
#define XS_STR 116
#define KR_STR 236
#define VR_STR 232
#define QT_STR 236
#define RT_STR 236
#define OT_STR 236
#define P_STR  76
#define XS_N (64 * XS_STR)     // 7424
#define KR_N (64 * KR_STR)     // 15104
#define VR_N (64 * VR_STR)     // 14848
#define QT_N (16 * QT_STR)     // 3776
#define RT_N (16 * RT_STR)     // 3776
#define SMEM3 ((XS_N + KR_N + VR_N + QT_N + RT_N + 256) * 4)   // 180736 B

__global__ void __launch_bounds__(448) k_attn(
        const float* __restrict__ hidden,
        const float* __restrict__ ln1g, const float* __restrict__ ln1b,
        const float* __restrict__ bp) {
    extern __shared__ float sm[];
    float* Xs   = sm;
    float* Krow = Xs + XS_N;
    float* Vrow = Krow + KR_N;
    float* Qt   = Vrow + VR_N;
    float* Rt   = Qt + QT_N;
    float* smax = Rt + RT_N;      // [64][2]
    float* ssum = smax + 128;     // [64][2]
    float* P    = Xs;    // alias (X dead after QKV)
    float* Ot   = Qt;    // alias (Qt dead after scores)

    int wi = blockIdx.x;
    int b  = wi >> 8;
    int r  = wi & 255;
    int wy = r >> 4, wx = r & 15;
    int tid  = threadIdx.x;
    int warp = tid >> 5, lane = tid & 31;
    int g = lane >> 2, tig = lane & 3;

    // ---- stage raw window ----
    for (int e = tid; e < 64 * 28; e += 448) {
        int t = e / 28, c4 = (e - t * 28) * 4;
        int y = wy * 8 + (t >> 3), x = wx * 8 + (t & 7);
        *(float4*)&Xs[t * XS_STR + c4] =
            *(const float4*)&hidden[(((size_t)b * 128 + y) * 128 + x) * 112 + c4];
    }
    __syncthreads();

    // ---- LN1 in place (warp per token), tf32-rounded ----
    {
        float gg0 = ln1g[lane], gg1 = ln1g[lane + 32], gg2 = ln1g[lane + 64];
        float bb0 = ln1b[lane], bb1 = ln1b[lane + 32], bb2 = ln1b[lane + 64];
        float gg3 = 0.f, bb3 = 0.f;
        if (lane < 16) { gg3 = ln1g[lane + 96]; bb3 = ln1b[lane + 96]; }
        for (int t = warp; t < 64; t += 14) {
            float* row = Xs + t * XS_STR;
            float v0 = row[lane], v1 = row[lane + 32], v2 = row[lane + 64];
            float v3 = (lane < 16) ? row[lane + 96] : 0.f;
            float s = v0 + v1 + v2 + v3;
            #pragma unroll
            for (int o = 16; o; o >>= 1) s += __shfl_xor_sync(~0u, s, o);
            float m = s * (1.f / 112.f);
            float d0 = v0 - m, d1 = v1 - m, d2 = v2 - m;
            float d3 = (lane < 16) ? v3 - m : 0.f;
            float q = d0*d0 + d1*d1 + d2*d2 + d3*d3;
            #pragma unroll
            for (int o = 16; o; o >>= 1) q += __shfl_xor_sync(~0u, q, o);
            float rs = rsqrtf(q * (1.f / 112.f) + 1e-6f);
            row[lane]      = rtf(d0 * rs * gg0 + bb0);
            row[lane + 32] = rtf(d1 * rs * gg1 + bb1);
            row[lane + 64] = rtf(d2 * rs * gg2 + bb2);
            if (lane < 16) row[lane + 96] = rtf(d3 * rs * gg3 + bb3);
        }
    }
    __syncthreads();

    // ---- QKV+R GEMM: M=64, N=896, K=112; warp n-slice 64, two j-passes of 4 ----
    {
        const unsigned* Xb = (const unsigned*)Xs;
        const unsigned* Wb = (const unsigned*)g_wbig;
        #pragma unroll
        for (int pass = 0; pass < 2; pass++) {
            int colbase = warp * 64 + pass * 32;
            float acc[4][4][4];
            #pragma unroll
            for (int j = 0; j < 4; j++) {
                int col = colbase + j * 8;
                float bv0 = g_bbig[col + 2 * tig];
                float bv1 = g_bbig[col + 2 * tig + 1];
                #pragma unroll
                for (int mt = 0; mt < 4; mt++) {
                    acc[mt][j][0] = bv0; acc[mt][j][1] = bv1;
                    acc[mt][j][2] = bv0; acc[mt][j][3] = bv1;
                }
            }
            for (int kc = 0; kc < 112; kc += 8) {
                unsigned a[4][4];
                #pragma unroll
                for (int mt = 0; mt < 4; mt++) {
                    int r0 = (mt * 16 + g) * XS_STR + kc;
                    int r1 = r0 + 8 * XS_STR;
                    a[mt][0] = Xb[r0 + tig];
                    a[mt][1] = Xb[r1 + tig];
                    a[mt][2] = Xb[r0 + tig + 4];
                    a[mt][3] = Xb[r1 + tig + 4];
                }
                #pragma unroll
                for (int j = 0; j < 4; j++) {
                    int col = colbase + j * 8 + g;
                    unsigned b0 = Wb[(kc + tig) * 896 + col];
                    unsigned b1 = Wb[(kc + tig + 4) * 896 + col];
                    #pragma unroll
                    for (int mt = 0; mt < 4; mt++)
                        mma_tf32(acc[mt][j], a[mt][0], a[mt][1], a[mt][2], a[mt][3], b0, b1);
                }
            }
            // routed stores (uniform branch per warp/j); K and V both row-major float2
            #pragma unroll
            for (int j = 0; j < 4; j++) {
                int col = colbase + j * 8;
                int mat = col / 224;
                int lc  = col - mat * 224;
                if (mat == 1 || mat == 2) {   // K or V -> row-major [t][d]
                    float* dst = (mat == 1) ? Krow : Vrow;
                    int str    = (mat == 1) ? KR_STR : VR_STR;
                    #pragma unroll
                    for (int mt = 0; mt < 4; mt++) {
                        int t0r = mt * 16 + g;
                        *(float2*)&dst[t0r * str + lc + 2*tig] =
                            make_float2(rtf(acc[mt][j][0]), rtf(acc[mt][j][1]));
                        *(float2*)&dst[(t0r + 8) * str + lc + 2*tig] =
                            make_float2(rtf(acc[mt][j][2]), rtf(acc[mt][j][3]));
                    }
                } else {                      // Q (mat 0) or R (mat 3): 2x2 pool in regs
                    #pragma unroll
                    for (int mt = 0; mt < 4; mt++) {
                        float m0 = fmaxf(acc[mt][j][0], acc[mt][j][2]);  // rows g, g+8
                        float m1 = fmaxf(acc[mt][j][1], acc[mt][j][3]);
                        m0 = fmaxf(m0, __shfl_xor_sync(~0u, m0, 4));     // lanes g ^ 1
                        m1 = fmaxf(m1, __shfl_xor_sync(~0u, m1, 4));
                        if (!(g & 1)) {
                            int q = mt * 4 + (g >> 1);
                            if (mat == 0)
                                *(float2*)&Qt[q * QT_STR + lc + 2*tig] =
                                    make_float2(rtf(m0), rtf(m1));
                            else
                                *(float2*)&Rt[q * RT_STR + lc + 2*tig] =
                                    make_float2(m0, m1);
                        }
                    }
                }
            }
        }
    }
    __syncthreads();

    // ---- scores + in-register softmax (8 warps) -> P (aliases Xs) ----
    const float scale = 0.13363062095621219f;   // 56^-0.5
    bool sa = (warp < 8);
    int sh = warp >> 1, snh = warp & 1;
    float sc[4][4];
    if (sa) {
        const unsigned* Qb = (const unsigned*)Qt;
        const unsigned* Kb = (const unsigned*)Krow;
        #pragma unroll
        for (int j = 0; j < 4; j++)
            #pragma unroll
            for (int e = 0; e < 4; e++) sc[j][e] = 0.f;
        #pragma unroll
        for (int kc = 0; kc < 56; kc += 8) {
            int kd = sh * 56 + kc;
            unsigned a0 = Qb[g * QT_STR + kd + tig];
            unsigned a1 = Qb[(g + 8) * QT_STR + kd + tig];
            unsigned a2 = Qb[g * QT_STR + kd + tig + 4];
            unsigned a3 = Qb[(g + 8) * QT_STR + kd + tig + 4];
            #pragma unroll
            for (int j = 0; j < 4; j++) {
                int n0 = snh * 32 + j * 8;
                unsigned b0 = Kb[(n0 + g) * KR_STR + kd + tig];
                unsigned b1 = Kb[(n0 + g) * KR_STR + kd + tig + 4];
                mma_tf32(sc[j], a0, a1, a2, a3, b0, b1);
            }
        }
        // per-warp (half-row) max via quad shuffles
        float m0 = -1e30f, m1 = -1e30f;
        #pragma unroll
        for (int j = 0; j < 4; j++) {
            sc[j][0] *= scale; sc[j][1] *= scale;
            sc[j][2] *= scale; sc[j][3] *= scale;
            m0 = fmaxf(m0, fmaxf(sc[j][0], sc[j][1]));
            m1 = fmaxf(m1, fmaxf(sc[j][2], sc[j][3]));
        }
        m0 = fmaxf(m0, __shfl_xor_sync(~0u, m0, 1));
        m0 = fmaxf(m0, __shfl_xor_sync(~0u, m0, 2));
        m1 = fmaxf(m1, __shfl_xor_sync(~0u, m1, 1));
        m1 = fmaxf(m1, __shfl_xor_sync(~0u, m1, 2));
        if (tig == 0) {
            smax[(sh * 16 + g) * 2 + snh]     = m0;
            smax[(sh * 16 + g + 8) * 2 + snh] = m1;
        }
    }
    __syncthreads();
    if (sa) {
        int r0 = sh * 16 + g, r1 = r0 + 8;
        float M0 = fmaxf(smax[r0 * 2], smax[r0 * 2 + 1]);
        float M1 = fmaxf(smax[r1 * 2], smax[r1 * 2 + 1]);
        float s0 = 0.f, s1 = 0.f;
        #pragma unroll
        for (int j = 0; j < 4; j++) {
            sc[j][0] = __expf(sc[j][0] - M0); sc[j][1] = __expf(sc[j][1] - M0);
            sc[j][2] = __expf(sc[j][2] - M1); sc[j][3] = __expf(sc[j][3] - M1);
            s0 += sc[j][0] + sc[j][1];
            s1 += sc[j][2] + sc[j][3];
        }
        s0 += __shfl_xor_sync(~0u, s0, 1); s0 += __shfl_xor_sync(~0u, s0, 2);
        s1 += __shfl_xor_sync(~0u, s1, 1); s1 += __shfl_xor_sync(~0u, s1, 2);
        if (tig == 0) {
            ssum[r0 * 2 + snh] = s0;
            ssum[r1 * 2 + snh] = s1;
        }
    }
    __syncthreads();
    if (sa) {
        int r0 = sh * 16 + g, r1 = r0 + 8;
        float inv0 = 1.f / (ssum[r0 * 2] + ssum[r0 * 2 + 1]);
        float inv1 = 1.f / (ssum[r1 * 2] + ssum[r1 * 2 + 1]);
        #pragma unroll
        for (int j = 0; j < 4; j++) {
            int n0 = snh * 32 + j * 8;
            *(float2*)&P[r0 * P_STR + n0 + 2*tig] =
                make_float2(rtf(sc[j][0] * inv0), rtf(sc[j][1] * inv0));
            *(float2*)&P[r1 * P_STR + n0 + 2*tig] =
                make_float2(rtf(sc[j][2] * inv1), rtf(sc[j][3] * inv1));
        }
    }
    __syncthreads();

    // ---- PV: per head 16x56x64 -> Ot (aliases Qt) ----
    {
        const unsigned* Pb = (const unsigned*)P;
        const unsigned* Vb = (const unsigned*)Vrow;
        #pragma unroll
        for (int ui = 0; ui < 2; ui++) {
            int u = warp * 2 + ui;        // 0..27
            int h = u / 7, j = u - h * 7;
            int n0 = h * 56 + j * 8;
            float acc[4] = {0.f, 0.f, 0.f, 0.f};
            #pragma unroll
            for (int kc = 0; kc < 64; kc += 8) {
                unsigned a0 = Pb[(h * 16 + g) * P_STR + kc + tig];
                unsigned a1 = Pb[(h * 16 + g + 8) * P_STR + kc + tig];
                unsigned a2 = Pb[(h * 16 + g) * P_STR + kc + tig + 4];
                unsigned a3 = Pb[(h * 16 + g + 8) * P_STR + kc + tig + 4];
                unsigned b0 = Vb[(kc + tig) * VR_STR + n0 + g];
                unsigned b1 = Vb[(kc + tig + 4) * VR_STR + n0 + g];
                mma_tf32(acc, a0, a1, a2, a3, b0, b1);
            }
            *(float2*)&Ot[g * OT_STR + n0 + 2*tig] =
                make_float2(rtf(acc[0]), rtf(acc[1]));
            *(float2*)&Ot[(g + 8) * OT_STR + n0 + 2*tig] =
                make_float2(rtf(acc[2]), rtf(acc[3]));
        }
    }
    __syncthreads();

    // ---- attn_proj (16x224x224), accumulate into Rt ----
    {
        const unsigned* Ob = (const unsigned*)Ot;
        int n0w = warp * 16;
        float acc[2][4];
        #pragma unroll
        for (int j = 0; j < 2; j++) {
            int col = n0w + j * 8;
            float bv0 = bp[col + 2 * tig];
            float bv1 = bp[col + 2 * tig + 1];
            acc[j][0] = bv0; acc[j][1] = bv1; acc[j][2] = bv0; acc[j][3] = bv1;
        }
        #pragma unroll 4
        for (int kc = 0; kc < 224; kc += 8) {
            unsigned a0 = Ob[g * OT_STR + kc + tig];
            unsigned a1 = Ob[(g + 8) * OT_STR + kc + tig];
            unsigned a2 = Ob[g * OT_STR + kc + tig + 4];
            unsigned a3 = Ob[(g + 8) * OT_STR + kc + tig + 4];
            #pragma unroll
            for (int j = 0; j < 2; j++) {
                int n0 = n0w + j * 8;
                unsigned b0 = __float_as_uint(g_wpt[(kc + tig) * 224 + n0 + g]);
                unsigned b1 = __float_as_uint(g_wpt[(kc + tig + 4) * 224 + n0 + g]);
                mma_tf32(acc[j], a0, a1, a2, a3, b0, b1);
            }
        }
        #pragma unroll
        for (int j = 0; j < 2; j++) {
            int d = n0w + j * 8 + 2 * tig;
            float2 r0v = *(float2*)&Rt[g * RT_STR + d];
            *(float2*)&Rt[g * RT_STR + d] =
                make_float2(r0v.x + acc[j][0], r0v.y + acc[j][1]);
            float2 r1v = *(float2*)&Rt[(g + 8) * RT_STR + d];
            *(float2*)&Rt[(g + 8) * RT_STR + d] =
                make_float2(r1v.x + acc[j][2], r1v.y + acc[j][3]);
        }
    }
    __syncthreads();

    // ---- coalesced writeout of hs = residual + proj ----
    for (int e = tid; e < 16 * 56; e += 448) {
        int q = e / 56, c4 = (e - q * 56) * 4;
        int y2 = wy * 4 + (q >> 2), x2 = wx * 4 + (q & 3);
        *(float4*)&g_hs[(((size_t)b * 64 + y2) * 64 + x2) * 224 + c4] =
            *(float4*)&Rt[q * RT_STR + c4];
    }
}

// ---------------------------------------------------------------------------
// K4: out = hs + MLP(LN2(hs)); 512 blocks x 448 threads (round-6/8, unchanged)
// ---------------------------------------------------------------------------
#define XLN_STR 228
#define HA_STR  452
#define SMEM4   ((64 * XLN_STR + 64 * HA_STR) * 4)   // 174080 B

__global__ void __launch_bounds__(448) k_mlp(
        const float* __restrict__ g2, const float* __restrict__ b2,
        const float* __restrict__ b1, const float* __restrict__ b2m,
        float* __restrict__ out) {
    extern __shared__ float sm[];
    float* Xln = sm;
    float* Ha  = sm + 64 * XLN_STR;

    int t0   = blockIdx.x * 64;
    int tid  = threadIdx.x;
    int warp = tid >> 5, lane = tid & 31;
    int g = lane >> 2, tig = lane & 3;

    {
        float gv[7], bv[7];
        #pragma unroll
        for (int k = 0; k < 7; k++) { gv[k] = g2[lane + 32*k]; bv[k] = b2[lane + 32*k]; }
        for (int t = warp; t < 64; t += 14) {
            const float* hr = &g_hs[(size_t)(t0 + t) * 224];
            float v[7]; float s = 0.f;
            #pragma unroll
            for (int k = 0; k < 7; k++) { v[k] = hr[lane + 32*k]; s += v[k]; }
            #pragma unroll
            for (int o = 16; o; o >>= 1) s += __shfl_xor_sync(~0u, s, o);
            float m = s * (1.f / 224.f);
            float q = 0.f;
            #pragma unroll
            for (int k = 0; k < 7; k++) { v[k] -= m; q += v[k] * v[k]; }
            #pragma unroll
            for (int o = 16; o; o >>= 1) q += __shfl_xor_sync(~0u, q, o);
            float rs = rsqrtf(q * (1.f / 224.f) + 1e-6f);
            #pragma unroll
            for (int k = 0; k < 7; k++)
                Xln[t * XLN_STR + lane + 32*k] = rtf(v[k] * rs * gv[k] + bv[k]);
        }
    }
    __syncthreads();

    const unsigned* Xb = (const unsigned*)Xln;
    const unsigned* Hb = (const unsigned*)Ha;
    const unsigned* W1 = (const unsigned*)g_w1t;
    const unsigned* W2 = (const unsigned*)g_w2t;

    int n0w = warp * 16;
    float acc2[4][2][4];
    #pragma unroll
    for (int j = 0; j < 2; j++) {
        float bv0 = b2m[n0w + j * 8 + 2 * tig];
        float bv1 = b2m[n0w + j * 8 + 2 * tig + 1];
        #pragma unroll
        for (int mt = 0; mt < 4; mt++) {
            acc2[mt][j][0] = bv0; acc2[mt][j][1] = bv1;
            acc2[mt][j][2] = bv0; acc2[mt][j][3] = bv1;
        }
    }

    #pragma unroll 1
    for (int hp = 0; hp < 2; hp++) {
        int hb = hp * 448;
        {
            int cb = hb + warp * 32;
            float acc1[4][4][4];
            #pragma unroll
            for (int j = 0; j < 4; j++) {
                float bv0 = b1[cb + j * 8 + 2 * tig];
                float bv1 = b1[cb + j * 8 + 2 * tig + 1];
                #pragma unroll
                for (int mt = 0; mt < 4; mt++) {
                    acc1[mt][j][0] = bv0; acc1[mt][j][1] = bv1;
                    acc1[mt][j][2] = bv0; acc1[mt][j][3] = bv1;
                }
            }
            for (int kc = 0; kc < 224; kc += 8) {
                unsigned a[4][4];
                #pragma unroll
                for (int mt = 0; mt < 4; mt++) {
                    int r0 = (mt * 16 + g) * XLN_STR + kc;
                    int r1 = r0 + 8 * XLN_STR;
                    a[mt][0] = Xb[r0 + tig];
                    a[mt][1] = Xb[r1 + tig];
                    a[mt][2] = Xb[r0 + tig + 4];
                    a[mt][3] = Xb[r1 + tig + 4];
                }
                #pragma unroll
                for (int j = 0; j < 4; j++) {
                    int col = cb + j * 8 + g;
                    unsigned w0 = W1[(kc + tig) * 896 + col];
                    unsigned w1 = W1[(kc + tig + 4) * 896 + col];
                    #pragma unroll
                    for (int mt = 0; mt < 4; mt++)
                        mma_tf32(acc1[mt][j], a[mt][0], a[mt][1], a[mt][2], a[mt][3], w0, w1);
                }
            }
            int lb = warp * 32;
            #pragma unroll
            for (int mt = 0; mt < 4; mt++)
                #pragma unroll
                for (int j = 0; j < 4; j++) {
                    int lh = lb + j * 8 + 2 * tig;
                    int m0 = mt * 16 + g;
                    float a0 = acc1[mt][j][0], a1 = acc1[mt][j][1];
                    float a2 = acc1[mt][j][2], a3 = acc1[mt][j][3];
                    *(float2*)&Ha[m0 * HA_STR + lh] = make_float2(
                        rtf(0.5f * a0 * (1.f + erff(a0 * 0.70710678118654752f))),
                        rtf(0.5f * a1 * (1.f + erff(a1 * 0.70710678118654752f))));
                    *(float2*)&Ha[(m0 + 8) * HA_STR + lh] = make_float2(
                        rtf(0.5f * a2 * (1.f + erff(a2 * 0.70710678118654752f))),
                        rtf(0.5f * a3 * (1.f + erff(a3 * 0.70710678118654752f))));
                }
        }
        __syncthreads();
        for (int kc = 0; kc < 448; kc += 8) {
            unsigned a[4][4];
            #pragma unroll
            for (int mt = 0; mt < 4; mt++) {
                int r0 = (mt * 16 + g) * HA_STR + kc;
                int r1 = r0 + 8 * HA_STR;
                a[mt][0] = Hb[r0 + tig];
                a[mt][1] = Hb[r1 + tig];
                a[mt][2] = Hb[r0 + tig + 4];
                a[mt][3] = Hb[r1 + tig + 4];
            }
            #pragma unroll
            for (int j = 0; j < 2; j++) {
                int col = n0w + j * 8 + g;
                unsigned w0 = W2[(hb + kc + tig) * 224 + col];
                unsigned w1 = W2[(hb + kc + tig + 4) * 224 + col];
                #pragma unroll
                for (int mt = 0; mt < 4; mt++)
                    mma_tf32(acc2[mt][j], a[mt][0], a[mt][1], a[mt][2], a[mt][3], w0, w1);
            }
        }
        __syncthreads();
    }

    #pragma unroll
    for (int mt = 0; mt < 4; mt++)
        #pragma unroll
        for (int j = 0; j < 2; j++) {
            int n = n0w + j * 8 + 2 * tig;
            int m0 = t0 + mt * 16 + g;
            float2 h0 = *(const float2*)&g_hs[(size_t)m0 * 224 + n];
            *(float2*)&out[(size_t)m0 * 224 + n] =
                make_float2(h0.x + acc2[mt][j][0], h0.y + acc2[mt][j][1]);
            float2 h1 = *(const float2*)&g_hs[(size_t)(m0 + 8) * 224 + n];
            *(float2*)&out[(size_t)(m0 + 8) * 224 + n] =
                make_float2(h1.x + acc2[mt][j][2], h1.y + acc2[mt][j][3]);
        }
}

// ---------------------------------------------------------------------------
extern "C" void kernel_launch(void* const* d_in, const int* in_sizes, int n_in,
                              void* d_out, int out_size) {
    const float* hidden   = (const float*)d_in[0];
    const float* ln1_g    = (const float*)d_in[1];
    const float* ln1_b    = (const float*)d_in[2];
    const float* qkv_w    = (const float*)d_in[3];
    const float* qkv_b    = (const float*)d_in[4];
    const float* aproj_w  = (const float*)d_in[5];
    const float* aproj_b  = (const float*)d_in[6];
    const float* rproj_w  = (const float*)d_in[7];
    const float* rproj_b  = (const float*)d_in[8];
    const float* ln2_g    = (const float*)d_in[9];
    const float* ln2_b    = (const float*)d_in[10];
    const float* mlp1_w   = (const float*)d_in[11];
    const float* mlp1_b   = (const float*)d_in[12];
    const float* mlp2_w   = (const float*)d_in[13];
    const float* mlp2_b   = (const float*)d_in[14];
    float* out = (float*)d_out;

    cudaFuncSetAttribute(k_attn, cudaFuncAttributeMaxDynamicSharedMemorySize, SMEM3);
    cudaFuncSetAttribute(k_mlp,  cudaFuncAttributeMaxDynamicSharedMemorySize, SMEM4);

    k_prep<<<196, 1024>>>(mlp1_w, mlp2_w, qkv_w, rproj_w, aproj_w, qkv_b, rproj_b);
    k_attn<<<2048, 448, SMEM3>>>(hidden, ln1_g, ln1_b, aproj_b);
    k_mlp<<<512, 448, SMEM4>>>(ln2_g, ln2_b, mlp1_b, mlp2_b, out);
}